// round 2
// baseline (speedup 1.0000x reference)
#include <cuda_runtime.h>
#include <cuda_bf16.h>

#define N_MAX   100000
#define E_TOT_MAX 1700000
#define IN_F    128
#define HID     64
#define NCLS    16

// ---------------- scratch (device globals; no allocation allowed) ----------
__device__ float g_h1 [N_MAX * HID];    // x @ W1
__device__ float g_hid[N_MAX * HID];    // relu(agg1 + b1)
__device__ float g_h2 [N_MAX * NCLS];   // hid @ W2
__device__ float g_es1[N_MAX], g_ed1[N_MAX];
__device__ float g_es2[N_MAX], g_ed2[N_MAX];
__device__ int   g_deg[N_MAX];
__device__ int   g_cur[N_MAX];
__device__ int   g_rowptr[N_MAX + 1];
__device__ int   g_srcs[E_TOT_MAX];
__device__ int   g_part[512];

// ---------------- helpers ----------------
__device__ __forceinline__ float warpMax(float v) {
    #pragma unroll
    for (int o = 16; o; o >>= 1) v = fmaxf(v, __shfl_xor_sync(0xffffffffu, v, o));
    return v;
}
__device__ __forceinline__ float warpSum(float v) {
    #pragma unroll
    for (int o = 16; o; o >>= 1) v += __shfl_xor_sync(0xffffffffu, v, o);
    return v;
}

// ---------------- kernels ----------------
__global__ void k_zero(int n) {
    int i = blockIdx.x * blockDim.x + threadIdx.x;
    if (i < n) { g_deg[i] = 0; g_cur[i] = 0; }
}

// GEMM1: g_h1 = x @ W1   (N x 128 @ 128 x 64), 64-row x 64-col tile per block
__global__ void k_gemm1(const float* __restrict__ x, const float* __restrict__ W1, int n) {
    __shared__ float xs[64][33];
    __shared__ float ws[32][64];
    int t = threadIdx.x;
    int br = blockIdx.x * 64;
    int tr = t >> 4, tc = t & 15;
    int r0 = tr * 4, c0 = tc * 4;
    float acc[4][4] = {};
    for (int kc = 0; kc < IN_F; kc += 32) {
        // load x tile 64 rows x 32 cols (512 float4)
        #pragma unroll
        for (int i4 = t; i4 < 512; i4 += 256) {
            int r = i4 >> 3, q = i4 & 7;
            int gr = br + r;
            float4 v = make_float4(0.f, 0.f, 0.f, 0.f);
            if (gr < n) v = *(const float4*)(x + (size_t)gr * IN_F + kc + q * 4);
            xs[r][q * 4 + 0] = v.x; xs[r][q * 4 + 1] = v.y;
            xs[r][q * 4 + 2] = v.z; xs[r][q * 4 + 3] = v.w;
        }
        // load W tile 32 x 64 (contiguous)
        #pragma unroll
        for (int i4 = t; i4 < 512; i4 += 256)
            ((float4*)ws)[i4] = ((const float4*)(W1 + kc * HID))[i4];
        __syncthreads();
        #pragma unroll
        for (int k = 0; k < 32; k++) {
            float a0 = xs[r0 + 0][k], a1 = xs[r0 + 1][k];
            float a2 = xs[r0 + 2][k], a3 = xs[r0 + 3][k];
            float4 b = *(const float4*)&ws[k][c0];
            acc[0][0] += a0 * b.x; acc[0][1] += a0 * b.y; acc[0][2] += a0 * b.z; acc[0][3] += a0 * b.w;
            acc[1][0] += a1 * b.x; acc[1][1] += a1 * b.y; acc[1][2] += a1 * b.z; acc[1][3] += a1 * b.w;
            acc[2][0] += a2 * b.x; acc[2][1] += a2 * b.y; acc[2][2] += a2 * b.z; acc[2][3] += a2 * b.w;
            acc[3][0] += a3 * b.x; acc[3][1] += a3 * b.y; acc[3][2] += a3 * b.z; acc[3][3] += a3 * b.w;
        }
        __syncthreads();
    }
    #pragma unroll
    for (int i = 0; i < 4; i++) {
        int gr = br + r0 + i;
        if (gr < n)
            *(float4*)(g_h1 + (size_t)gr * HID + c0) =
                make_float4(acc[i][0], acc[i][1], acc[i][2], acc[i][3]);
    }
}

// per-node attention logits for layer 1: warp per node
__global__ void k_esd1(const float* __restrict__ as1, const float* __restrict__ ad1, int n) {
    int w = (blockIdx.x * blockDim.x + threadIdx.x) >> 5;
    int lane = threadIdx.x & 31;
    if (w >= n) return;
    float v0 = g_h1[(size_t)w * HID + lane];
    float v1 = g_h1[(size_t)w * HID + 32 + lane];
    float es = v0 * as1[lane] + v1 * as1[lane + 32];
    float ed = v0 * ad1[lane] + v1 * ad1[lane + 32];
    es = warpSum(es); ed = warpSum(ed);
    if (lane == 0) { g_es1[w] = es; g_ed1[w] = ed; }
}

__global__ void k_hist(const int* __restrict__ ei, int E, int ET) {
    int e = blockIdx.x * blockDim.x + threadIdx.x;
    if (e >= ET) return;
    int dst = (e < E) ? ei[E + e] : (e - E);
    atomicAdd(&g_deg[dst], 1);
}

__global__ void k_scan_a(int n) {
    __shared__ int s[1024];
    int t = threadIdx.x;
    int i = blockIdx.x * 1024 + t;
    int v = (i < n) ? g_deg[i] : 0;
    s[t] = v;
    #pragma unroll
    for (int off = 1; off < 1024; off <<= 1) {
        __syncthreads();
        int add = (t >= off) ? s[t - off] : 0;
        __syncthreads();
        s[t] += add;
    }
    __syncthreads();
    if (i < n) g_rowptr[i + 1] = s[t];
    if (t == 1023) g_part[blockIdx.x] = s[1023];
}

__global__ void k_scan_b(int nsb) {
    __shared__ int s[512];
    int t = threadIdx.x;
    s[t] = (t < nsb) ? g_part[t] : 0;
    #pragma unroll
    for (int off = 1; off < 512; off <<= 1) {
        __syncthreads();
        int add = (t >= off) ? s[t - off] : 0;
        __syncthreads();
        s[t] += add;
    }
    __syncthreads();
    if (t < nsb) g_part[t] = (t == 0) ? 0 : s[t - 1];  // exclusive
}

__global__ void k_scan_c(int n) {
    int t = threadIdx.x;
    int i = blockIdx.x * 1024 + t;
    if (i < n) g_rowptr[i + 1] += g_part[blockIdx.x];
    if (i == 0) g_rowptr[0] = 0;
}

__global__ void k_scatter(const int* __restrict__ ei, int E, int ET) {
    int e = blockIdx.x * blockDim.x + threadIdx.x;
    if (e >= ET) return;
    int src, dst;
    if (e < E) { src = ei[e]; dst = ei[E + e]; }
    else       { src = e - E; dst = e - E; }
    int pos = g_rowptr[dst] + atomicAdd(&g_cur[dst], 1);
    g_srcs[pos] = src;
}

// aggregation layer 1: warp per dst node, softmax-weighted sum of h1[src], +b1, relu
__global__ void k_agg1(const float* __restrict__ b1, int n) {
    int w = (blockIdx.x * blockDim.x + threadIdx.x) >> 5;
    int lane = threadIdx.x & 31;
    if (w >= n) return;
    int beg = g_rowptr[w], end = g_rowptr[w + 1];
    int deg = end - beg;
    float ed = g_ed1[w];
    float my_e = 0.f; int my_s = 0;
    float m = -1e30f;
    for (int j = lane; j < deg; j += 32) {
        int s = g_srcs[beg + j];
        float e = g_es1[s] + ed;
        e = (e >= 0.f) ? e : 0.2f * e;
        if (j < 32) { my_s = s; my_e = e; }
        m = fmaxf(m, e);
    }
    m = warpMax(m);
    float z = 0.f, a0 = 0.f, a1 = 0.f;
    int lim = deg < 32 ? deg : 32;
    for (int j = 0; j < lim; j++) {
        int   s = __shfl_sync(0xffffffffu, my_s, j);
        float e = __shfl_sync(0xffffffffu, my_e, j);
        float wt = __expf(e - m);
        z  += wt;
        a0 += wt * g_h1[(size_t)s * HID + lane];
        a1 += wt * g_h1[(size_t)s * HID + 32 + lane];
    }
    for (int j = 32; j < deg; j++) {
        int s = g_srcs[beg + j];
        float e = g_es1[s] + ed;
        e = (e >= 0.f) ? e : 0.2f * e;
        float wt = __expf(e - m);
        z  += wt;
        a0 += wt * g_h1[(size_t)s * HID + lane];
        a1 += wt * g_h1[(size_t)s * HID + 32 + lane];
    }
    float inv = 1.f / z;
    float v0 = a0 * inv + b1[lane];
    float v1 = a1 * inv + b1[lane + 32];
    g_hid[(size_t)w * HID + lane]      = v0 > 0.f ? v0 : 0.f;
    g_hid[(size_t)w * HID + 32 + lane] = v1 > 0.f ? v1 : 0.f;
}

// GEMM2: g_h2 = g_hid @ W2 (64->16), plus es2/ed2. thread per node.
__global__ void k_gemm2(const float* __restrict__ W2, const float* __restrict__ as2,
                        const float* __restrict__ ad2, int n) {
    __shared__ float4 ws[64][4];
    __shared__ float s_as[16], s_ad[16];
    int t = threadIdx.x;
    if (t < 256) ((float4*)ws)[t] = ((const float4*)W2)[t];
    if (t < 16) { s_as[t] = as2[t]; s_ad[t] = ad2[t]; }
    __syncthreads();
    int nidx = blockIdx.x * blockDim.x + t;
    if (nidx >= n) return;
    float acc[16];
    #pragma unroll
    for (int j = 0; j < 16; j++) acc[j] = 0.f;
    const float4* row = (const float4*)(g_hid + (size_t)nidx * HID);
    #pragma unroll
    for (int k4 = 0; k4 < 16; k4++) {
        float4 h = row[k4];
        float hv[4] = {h.x, h.y, h.z, h.w};
        #pragma unroll
        for (int kk = 0; kk < 4; kk++) {
            int k = k4 * 4 + kk;
            float4 w0 = ws[k][0], w1 = ws[k][1], w2 = ws[k][2], w3 = ws[k][3];
            float v = hv[kk];
            acc[0]  += v * w0.x; acc[1]  += v * w0.y; acc[2]  += v * w0.z; acc[3]  += v * w0.w;
            acc[4]  += v * w1.x; acc[5]  += v * w1.y; acc[6]  += v * w1.z; acc[7]  += v * w1.w;
            acc[8]  += v * w2.x; acc[9]  += v * w2.y; acc[10] += v * w2.z; acc[11] += v * w2.w;
            acc[12] += v * w3.x; acc[13] += v * w3.y; acc[14] += v * w3.z; acc[15] += v * w3.w;
        }
    }
    float es = 0.f, ed = 0.f;
    #pragma unroll
    for (int j = 0; j < 16; j++) { es += acc[j] * s_as[j]; ed += acc[j] * s_ad[j]; }
    float4* out = (float4*)(g_h2 + (size_t)nidx * NCLS);
    out[0] = make_float4(acc[0],  acc[1],  acc[2],  acc[3]);
    out[1] = make_float4(acc[4],  acc[5],  acc[6],  acc[7]);
    out[2] = make_float4(acc[8],  acc[9],  acc[10], acc[11]);
    out[3] = make_float4(acc[12], acc[13], acc[14], acc[15]);
    g_es2[nidx] = es; g_ed2[nidx] = ed;
}

// aggregation layer 2 + bias + log_softmax, warp per dst node
__global__ void k_agg2(const float* __restrict__ b2, float* __restrict__ out, int n) {
    int w = (blockIdx.x * blockDim.x + threadIdx.x) >> 5;
    int lane = threadIdx.x & 31;
    if (w >= n) return;
    int beg = g_rowptr[w], end = g_rowptr[w + 1];
    int deg = end - beg;
    float ed = g_ed2[w];
    float my_e = 0.f; int my_s = 0;
    float m = -1e30f;
    for (int j = lane; j < deg; j += 32) {
        int s = g_srcs[beg + j];
        float e = g_es2[s] + ed;
        e = (e >= 0.f) ? e : 0.2f * e;
        if (j < 32) { my_s = s; my_e = e; }
        m = fmaxf(m, e);
    }
    m = warpMax(m);
    float z = 0.f, acc = 0.f;
    int lim = deg < 32 ? deg : 32;
    for (int j = 0; j < lim; j++) {
        int   s = __shfl_sync(0xffffffffu, my_s, j);
        float e = __shfl_sync(0xffffffffu, my_e, j);
        float wt = __expf(e - m);
        z += wt;
        if (lane < 16) acc += wt * g_h2[(size_t)s * NCLS + lane];
    }
    for (int j = 32; j < deg; j++) {
        int s = g_srcs[beg + j];
        float e = g_es2[s] + ed;
        e = (e >= 0.f) ? e : 0.2f * e;
        float wt = __expf(e - m);
        z += wt;
        if (lane < 16) acc += wt * g_h2[(size_t)s * NCLS + lane];
    }
    float inv = 1.f / z;
    float val = (lane < 16) ? (acc * inv + b2[lane]) : -1e30f;
    // log_softmax over the 16 classes (within lower 16-lane group)
    float mx = val;
    #pragma unroll
    for (int o = 8; o; o >>= 1) mx = fmaxf(mx, __shfl_xor_sync(0xffffffffu, mx, o, 16));
    float ex = (lane < 16) ? __expf(val - mx) : 0.f;
    float se = ex;
    #pragma unroll
    for (int o = 8; o; o >>= 1) se += __shfl_xor_sync(0xffffffffu, se, o, 16);
    if (lane < 16) out[(size_t)w * NCLS + lane] = val - mx - logf(se);
}

// ---------------- launch ----------------
extern "C" void kernel_launch(void* const* d_in, const int* in_sizes, int n_in,
                              void* d_out, int out_size) {
    const float* x   = (const float*)d_in[0];
    const int*   ei  = (const int*)d_in[1];     // JAX default: int64 request -> int32
    const float* W1  = (const float*)d_in[2];
    const float* as1 = (const float*)d_in[3];
    const float* ad1 = (const float*)d_in[4];
    const float* b1  = (const float*)d_in[5];
    const float* W2  = (const float*)d_in[6];
    const float* as2 = (const float*)d_in[7];
    const float* ad2 = (const float*)d_in[8];
    const float* b2  = (const float*)d_in[9];
    float* out = (float*)d_out;

    int N  = in_sizes[0] / IN_F;
    int E  = in_sizes[1] / 2;
    int ET = E + N;
    int nsb = (N + 1023) / 1024;

    k_zero   <<<(N + 255) / 256, 256>>>(N);
    k_gemm1  <<<(N + 63) / 64, 256>>>(x, W1, N);
    k_esd1   <<<(N + 7) / 8, 256>>>(as1, ad1, N);
    k_hist   <<<(ET + 255) / 256, 256>>>(ei, E, ET);
    k_scan_a <<<nsb, 1024>>>(N);
    k_scan_b <<<1, 512>>>(nsb);
    k_scan_c <<<nsb, 1024>>>(N);
    k_scatter<<<(ET + 255) / 256, 256>>>(ei, E, ET);
    k_agg1   <<<(N + 7) / 8, 256>>>(b1, N);
    k_gemm2  <<<(N + 255) / 256, 256>>>(W2, as2, ad2, N);
    k_agg2   <<<(N + 7) / 8, 256>>>(b2, out, N);
}

// round 3
// speedup vs baseline: 1.1009x; 1.1009x over previous
#include <cuda_runtime.h>
#include <cuda_bf16.h>

#define N_MAX   100000
#define E_TOT_MAX 1700000
#define IN_F    128
#define HID     64
#define NCLS    16

// ---------------- scratch (device globals) ----------------
__device__ float g_h1 [N_MAX * HID];
__device__ float g_hid[N_MAX * HID];
__device__ float g_h2 [N_MAX * NCLS];
__device__ float g_es1[N_MAX], g_ed1[N_MAX];
__device__ float g_es2[N_MAX], g_ed2[N_MAX];
__device__ int   g_deg[N_MAX];
__device__ int   g_cur[N_MAX];
__device__ int   g_rowptr[N_MAX + 1];
__device__ int   g_srcs[E_TOT_MAX];
__device__ int   g_part[512];

// ---------------- helpers ----------------
__device__ __forceinline__ float warpMax(float v) {
    #pragma unroll
    for (int o = 16; o; o >>= 1) v = fmaxf(v, __shfl_xor_sync(0xffffffffu, v, o));
    return v;
}
__device__ __forceinline__ float warpSum(float v) {
    #pragma unroll
    for (int o = 16; o; o >>= 1) v += __shfl_xor_sync(0xffffffffu, v, o);
    return v;
}
// packed f32x2 (sm_100a, PTX ISA 8.6) — ptxas never auto-fuses these
__device__ __forceinline__ unsigned long long pk2(float v) {
    unsigned long long r;
    asm("mov.b64 %0, {%1, %1};" : "=l"(r) : "f"(v));
    return r;
}
__device__ __forceinline__ unsigned long long fma2(unsigned long long a,
                                                   unsigned long long b,
                                                   unsigned long long c) {
    unsigned long long d;
    asm("fma.rn.f32x2 %0, %1, %2, %3;" : "=l"(d) : "l"(a), "l"(b), "l"(c));
    return d;
}
__device__ __forceinline__ float2 upk(unsigned long long p) {
    float2 f;
    asm("mov.b64 {%0, %1}, %2;" : "=f"(f.x), "=f"(f.y) : "l"(p));
    return f;
}

// ---------------- kernels ----------------
__global__ void k_zero(int n) {
    int i = blockIdx.x * blockDim.x + threadIdx.x;
    if (i < n) g_deg[i] = 0;
}

// GEMM1 (fused es1/ed1): g_h1 = x @ W1, 64x64 tile, packed f32x2 math
__global__ void k_gemm1(const float* __restrict__ x, const float* __restrict__ W1,
                        const float* __restrict__ as1, const float* __restrict__ ad1,
                        int n) {
    __shared__ float xs[64][33];
    __shared__ float ws[32][64];
    __shared__ float esr[64][17];
    __shared__ float edr[64][17];
    int t = threadIdx.x;
    int br = blockIdx.x * 64;
    int tr = t >> 4, tc = t & 15;
    int r0 = tr * 4, c0 = tc * 4;
    unsigned long long accp[4][2] = {};
    for (int kc = 0; kc < IN_F; kc += 32) {
        #pragma unroll
        for (int i4 = t; i4 < 512; i4 += 256) {
            int r = i4 >> 3, q = i4 & 7;
            int gr = br + r;
            float4 v = make_float4(0.f, 0.f, 0.f, 0.f);
            if (gr < n) v = *(const float4*)(x + (size_t)gr * IN_F + kc + q * 4);
            xs[r][q * 4 + 0] = v.x; xs[r][q * 4 + 1] = v.y;
            xs[r][q * 4 + 2] = v.z; xs[r][q * 4 + 3] = v.w;
        }
        #pragma unroll
        for (int i4 = t; i4 < 512; i4 += 256)
            ((float4*)ws)[i4] = ((const float4*)(W1 + kc * HID))[i4];
        __syncthreads();
        #pragma unroll 4
        for (int k = 0; k < 32; k++) {
            unsigned long long pa0 = pk2(xs[r0 + 0][k]);
            unsigned long long pa1 = pk2(xs[r0 + 1][k]);
            unsigned long long pa2 = pk2(xs[r0 + 2][k]);
            unsigned long long pa3 = pk2(xs[r0 + 3][k]);
            const unsigned long long* wp = (const unsigned long long*)&ws[k][c0];
            unsigned long long b0 = wp[0], b1 = wp[1];
            accp[0][0] = fma2(pa0, b0, accp[0][0]); accp[0][1] = fma2(pa0, b1, accp[0][1]);
            accp[1][0] = fma2(pa1, b0, accp[1][0]); accp[1][1] = fma2(pa1, b1, accp[1][1]);
            accp[2][0] = fma2(pa2, b0, accp[2][0]); accp[2][1] = fma2(pa2, b1, accp[2][1]);
            accp[3][0] = fma2(pa3, b0, accp[3][0]); accp[3][1] = fma2(pa3, b1, accp[3][1]);
        }
        __syncthreads();
    }
    float as_l[4], ad_l[4];
    #pragma unroll
    for (int j = 0; j < 4; j++) { as_l[j] = as1[c0 + j]; ad_l[j] = ad1[c0 + j]; }
    #pragma unroll
    for (int i = 0; i < 4; i++) {
        float2 p0 = upk(accp[i][0]), p1 = upk(accp[i][1]);
        float a0 = p0.x, a1 = p0.y, a2 = p1.x, a3 = p1.y;
        int gr = br + r0 + i;
        if (gr < n)
            *(float4*)(g_h1 + (size_t)gr * HID + c0) = make_float4(a0, a1, a2, a3);
        esr[r0 + i][tc] = a0 * as_l[0] + a1 * as_l[1] + a2 * as_l[2] + a3 * as_l[3];
        edr[r0 + i][tc] = a0 * ad_l[0] + a1 * ad_l[1] + a2 * ad_l[2] + a3 * ad_l[3];
    }
    __syncthreads();
    if (t < 64) {
        int gr = br + t;
        if (gr < n) {
            float es = 0.f, ed = 0.f;
            #pragma unroll
            for (int c = 0; c < 16; c++) { es += esr[t][c]; ed += edr[t][c]; }
            g_es1[gr] = es; g_ed1[gr] = ed;
        }
    }
}

__global__ void k_hist(const int* __restrict__ ei, int E, int ET) {
    int e = blockIdx.x * blockDim.x + threadIdx.x;
    if (e >= ET) return;
    int dst = (e < E) ? ei[E + e] : (e - E);
    atomicAdd(&g_deg[dst], 1);
}

__global__ void k_scan_a(int n) {
    __shared__ int s[1024];
    int t = threadIdx.x;
    int i = blockIdx.x * 1024 + t;
    int v = (i < n) ? g_deg[i] : 0;
    s[t] = v;
    #pragma unroll
    for (int off = 1; off < 1024; off <<= 1) {
        __syncthreads();
        int add = (t >= off) ? s[t - off] : 0;
        __syncthreads();
        s[t] += add;
    }
    __syncthreads();
    if (i < n) g_rowptr[i + 1] = s[t];
    if (t == 1023) g_part[blockIdx.x] = s[1023];
}

__global__ void k_scan_b(int nsb) {
    __shared__ int s[512];
    int t = threadIdx.x;
    s[t] = (t < nsb) ? g_part[t] : 0;
    #pragma unroll
    for (int off = 1; off < 512; off <<= 1) {
        __syncthreads();
        int add = (t >= off) ? s[t - off] : 0;
        __syncthreads();
        s[t] += add;
    }
    __syncthreads();
    if (t < nsb) g_part[t] = (t == 0) ? 0 : s[t - 1];  // exclusive
}

__global__ void k_scan_c(int n) {
    int t = threadIdx.x;
    int i = blockIdx.x * 1024 + t;
    if (i < n) {
        int v = g_rowptr[i + 1] + g_part[blockIdx.x];
        g_rowptr[i + 1] = v;
        if (i + 1 < n) g_cur[i + 1] = v;   // exclusive prefix -> running cursor
    }
    if (i == 0) { g_rowptr[0] = 0; g_cur[0] = 0; }
}

__global__ void k_scatter(const int* __restrict__ ei, int E, int ET) {
    int e = blockIdx.x * blockDim.x + threadIdx.x;
    if (e >= ET) return;
    int src, dst;
    if (e < E) { src = ei[e]; dst = ei[E + e]; }
    else       { src = e - E; dst = e - E; }
    int pos = atomicAdd(&g_cur[dst], 1);
    g_srcs[pos] = src;
}

// aggregation layer 1: warp per dst, lane owns feature pair 2*lane
__global__ void k_agg1(const float* __restrict__ b1, int n) {
    int w = (blockIdx.x * blockDim.x + threadIdx.x) >> 5;
    int lane = threadIdx.x & 31;
    if (w >= n) return;
    int beg = g_rowptr[w];
    int deg = g_rowptr[w + 1] - beg;
    float ed = g_ed1[w];
    float my_e = 0.f; int my_s = 0;
    float m = -1e30f;
    for (int j = lane; j < deg; j += 32) {
        int s = g_srcs[beg + j];
        float e = g_es1[s] + ed;
        e = (e >= 0.f) ? e : 0.2f * e;
        if (j < 32) { my_s = s; my_e = e; }
        m = fmaxf(m, e);
    }
    m = warpMax(m);
    float z = 0.f;
    unsigned long long acc = 0ULL;
    int lim = deg < 32 ? deg : 32;
    for (int j = 0; j < lim; j++) {
        int   s = __shfl_sync(0xffffffffu, my_s, j);
        float e = __shfl_sync(0xffffffffu, my_e, j);
        float wt = __expf(e - m);
        z += wt;
        unsigned long long h = ((const unsigned long long*)(g_h1 + (size_t)s * HID))[lane];
        acc = fma2(pk2(wt), h, acc);
    }
    #pragma unroll 2
    for (int j = 32; j < deg; j++) {
        int s = g_srcs[beg + j];
        float e = g_es1[s] + ed;
        e = (e >= 0.f) ? e : 0.2f * e;
        float wt = __expf(e - m);
        z += wt;
        unsigned long long h = ((const unsigned long long*)(g_h1 + (size_t)s * HID))[lane];
        acc = fma2(pk2(wt), h, acc);
    }
    float inv = 1.f / z;
    float2 r = upk(acc);
    float2 bb = ((const float2*)b1)[lane];
    float v0 = r.x * inv + bb.x;
    float v1 = r.y * inv + bb.y;
    float2 o;
    o.x = v0 > 0.f ? v0 : 0.f;
    o.y = v1 > 0.f ? v1 : 0.f;
    ((float2*)(g_hid + (size_t)w * HID))[lane] = o;
}

// GEMM2 (fused es2/ed2): g_h2 = g_hid @ W2, thread per node, packed f32x2
__global__ void k_gemm2(const float* __restrict__ W2, const float* __restrict__ as2,
                        const float* __restrict__ ad2, int n) {
    __shared__ float ws2[64][16];
    __shared__ float s_as[16], s_ad[16];
    int t = threadIdx.x;
    if (t < 256) ((float4*)ws2)[t] = ((const float4*)W2)[t];
    if (t < 16) { s_as[t] = as2[t]; s_ad[t] = ad2[t]; }
    __syncthreads();
    int nidx = blockIdx.x * blockDim.x + t;
    if (nidx >= n) return;
    unsigned long long accp[8] = {};
    const float4* row = (const float4*)(g_hid + (size_t)nidx * HID);
    #pragma unroll
    for (int k4 = 0; k4 < 16; k4++) {
        float4 h = row[k4];
        float hv[4] = {h.x, h.y, h.z, h.w};
        #pragma unroll
        for (int kk = 0; kk < 4; kk++) {
            int k = k4 * 4 + kk;
            unsigned long long pv = pk2(hv[kk]);
            const unsigned long long* wp = (const unsigned long long*)&ws2[k][0];
            #pragma unroll
            for (int p = 0; p < 8; p++) accp[p] = fma2(pv, wp[p], accp[p]);
        }
    }
    float a[16];
    #pragma unroll
    for (int p = 0; p < 8; p++) { float2 u = upk(accp[p]); a[2 * p] = u.x; a[2 * p + 1] = u.y; }
    float es = 0.f, ed = 0.f;
    #pragma unroll
    for (int j = 0; j < 16; j++) { es += a[j] * s_as[j]; ed += a[j] * s_ad[j]; }
    float4* outp = (float4*)(g_h2 + (size_t)nidx * NCLS);
    outp[0] = make_float4(a[0],  a[1],  a[2],  a[3]);
    outp[1] = make_float4(a[4],  a[5],  a[6],  a[7]);
    outp[2] = make_float4(a[8],  a[9],  a[10], a[11]);
    outp[3] = make_float4(a[12], a[13], a[14], a[15]);
    g_es2[nidx] = es; g_ed2[nidx] = ed;
}

// aggregation layer 2 + bias + log_softmax: warp per dst, 2 edges/iter
__global__ void k_agg2(const float* __restrict__ b2, float* __restrict__ out, int n) {
    int w = (blockIdx.x * blockDim.x + threadIdx.x) >> 5;
    int lane = threadIdx.x & 31;
    if (w >= n) return;
    int beg = g_rowptr[w];
    int deg = g_rowptr[w + 1] - beg;
    float ed = g_ed2[w];
    float my_e = 0.f; int my_s = 0;
    float m = -1e30f;
    for (int j = lane; j < deg; j += 32) {
        int s = g_srcs[beg + j];
        float e = g_es2[s] + ed;
        e = (e >= 0.f) ? e : 0.2f * e;
        if (j < 32) { my_s = s; my_e = e; }
        m = fmaxf(m, e);
    }
    m = warpMax(m);
    // z pass (per-lane, no feature loads)
    float z = 0.f;
    if (lane < deg) z = __expf(my_e - m);
    for (int j = lane + 32; j < deg; j += 32) {
        int s = g_srcs[beg + j];
        float e = g_es2[s] + ed;
        e = (e >= 0.f) ? e : 0.2f * e;
        z += __expf(e - m);
    }
    z = warpSum(z);
    // paired accumulate: lanes 0-15 -> even edges, 16-31 -> odd edges (shfl range only)
    int half = lane >> 4, fl = lane & 15;
    int lim2 = (deg < 32 ? deg : 32) & ~1;   // even, <=32: both halves stay in shfl path
    float acc = 0.f;
    for (int jb = 0; jb < lim2; jb += 2) {
        int j = jb + half;
        int   s = __shfl_sync(0xffffffffu, my_s, j);
        float e = __shfl_sync(0xffffffffu, my_e, j);
        float wt = __expf(e - m);
        acc += wt * g_h2[(size_t)s * NCLS + fl];
    }
    acc += __shfl_xor_sync(0xffffffffu, acc, 16);
    // leftover edges: whole warp per edge, lanes<16 accumulate
    for (int j = lim2; j < deg; j++) {
        int s; float e;
        if (j < 32) {
            s = __shfl_sync(0xffffffffu, my_s, j);
            e = __shfl_sync(0xffffffffu, my_e, j);
        } else {
            s = g_srcs[beg + j];
            e = g_es2[s] + ed;
            e = (e >= 0.f) ? e : 0.2f * e;
        }
        float wt = __expf(e - m);
        if (lane < 16) acc += wt * g_h2[(size_t)s * NCLS + lane];
    }
    float inv = 1.f / z;
    float val = (lane < 16) ? (acc * inv + b2[fl]) : -1e30f;
    float mx = val;
    #pragma unroll
    for (int o = 8; o; o >>= 1) mx = fmaxf(mx, __shfl_xor_sync(0xffffffffu, mx, o, 16));
    float ex = (lane < 16) ? __expf(val - mx) : 0.f;
    float se = ex;
    #pragma unroll
    for (int o = 8; o; o >>= 1) se += __shfl_xor_sync(0xffffffffu, se, o, 16);
    if (lane < 16) out[(size_t)w * NCLS + fl] = val - mx - logf(se);
}

// ---------------- launch ----------------
extern "C" void kernel_launch(void* const* d_in, const int* in_sizes, int n_in,
                              void* d_out, int out_size) {
    const float* x   = (const float*)d_in[0];
    const int*   ei  = (const int*)d_in[1];
    const float* W1  = (const float*)d_in[2];
    const float* as1 = (const float*)d_in[3];
    const float* ad1 = (const float*)d_in[4];
    const float* b1  = (const float*)d_in[5];
    const float* W2  = (const float*)d_in[6];
    const float* as2 = (const float*)d_in[7];
    const float* ad2 = (const float*)d_in[8];
    const float* b2  = (const float*)d_in[9];
    float* out = (float*)d_out;

    int N  = in_sizes[0] / IN_F;
    int E  = in_sizes[1] / 2;
    int ET = E + N;
    int nsb = (N + 1023) / 1024;

    k_zero   <<<(N + 255) / 256, 256>>>(N);
    k_gemm1  <<<(N + 63) / 64, 256>>>(x, W1, as1, ad1, N);
    k_hist   <<<(ET + 255) / 256, 256>>>(ei, E, ET);
    k_scan_a <<<nsb, 1024>>>(N);
    k_scan_b <<<1, 512>>>(nsb);
    k_scan_c <<<nsb, 1024>>>(N);
    k_scatter<<<(ET + 255) / 256, 256>>>(ei, E, ET);
    k_agg1   <<<(N + 7) / 8, 256>>>(b1, N);
    k_gemm2  <<<(N + 255) / 256, 256>>>(W2, as2, ad2, N);
    k_agg2   <<<(N + 7) / 8, 256>>>(b2, out, N);
}